// round 13
// baseline (speedup 1.0000x reference)
#include <cuda_runtime.h>
#include <cuda_bf16.h>
#include <cstdint>
#include <math.h>

#define B_ 1024
#define H_ 512
#define T_ 10

typedef __nv_bfloat16 bf16;

__device__ bf16  g_pool1[B_*196*64];
__device__ bf16  g_conv2[B_*196*128];
__device__ bf16  g_pool2[B_*36*128];
__device__ bf16  g_conv3[B_*16*128];
__device__ bf16  g_conv4[B_*4*256];
__device__ bf16  g_emb[B_*256];
__device__ float g_embproj[B_*2048];
__device__ bf16  g_h[B_*H_];
__device__ float g_c[B_*H_];
__device__ float g_gates[B_*2048];
__device__ float g_wT[66*2048];
__device__ bf16  g_w2t[128*576];
__device__ bf16  g_w3t[128*1152];
__device__ bf16  g_w4t[256*1152];
__device__ bf16  g_wih2[2048*256];
__device__ bf16  g_whh[2048*512];
__device__ unsigned g_cnt, g_gen;

__device__ __forceinline__ void mma16(float4& d, uint32_t a0, uint32_t a1,
        uint32_t a2, uint32_t a3, uint32_t b0, uint32_t b1) {
    asm volatile(
        "mma.sync.aligned.m16n8k16.row.col.f32.bf16.bf16.f32 "
        "{%0,%1,%2,%3}, {%4,%5,%6,%7}, {%8,%9}, {%0,%1,%2,%3};\n"
        : "+f"(d.x), "+f"(d.y), "+f"(d.z), "+f"(d.w)
        : "r"(a0), "r"(a1), "r"(a2), "r"(a3), "r"(b0), "r"(b1));
}
__device__ __forceinline__ void ldsm4(uint32_t& r0, uint32_t& r1,
        uint32_t& r2, uint32_t& r3, uint32_t addr) {
    asm volatile("ldmatrix.sync.aligned.m8n8.x4.shared.b16 {%0,%1,%2,%3}, [%4];"
                 : "=r"(r0), "=r"(r1), "=r"(r2), "=r"(r3) : "r"(addr));
}
__device__ __forceinline__ void cp16(uint32_t dst, const void* src, bool v) {
    int sz = v ? 16 : 0;
    asm volatile("cp.async.cg.shared.global [%0], [%1], 16, %2;\n"
                 :: "r"(dst), "l"(src), "r"(sz));
}

// grid barrier: 128 co-resident blocks
__device__ __forceinline__ void gsync() {
    __syncthreads();
    if (threadIdx.x == 0) {
        __threadfence();
        unsigned g = atomicAdd(&g_gen, 0u);
        if (atomicAdd(&g_cnt, 1u) == 127u) {
            atomicExch(&g_cnt, 0u);
            __threadfence();
            atomicAdd(&g_gen, 1u);
        } else {
            while (atomicAdd(&g_gen, 0u) == g) { }
        }
        __threadfence();
    }
    __syncthreads();
}

__global__ void init_kernel() {
    int idx = blockIdx.x*256 + threadIdx.x;
    if (idx < B_*H_) g_c[idx] = 0.f;
    if (idx == 0) { g_cnt = 0u; g_gen = 0u; }
}

__global__ void prep_kernel(const float* __restrict__ cw2,
                            const float* __restrict__ cw3,
                            const float* __restrict__ cw4,
                            const float* __restrict__ w_ih,
                            const float* __restrict__ w_hh) {
    int i = blockIdx.x*256 + threadIdx.x;
    if (i < 73728) {
        int oc = i/576, k = i%576, kyx = k >> 6, ic = k & 63;
        g_w2t[i] = __float2bfloat16_rn(cw2[oc*576 + ic*9 + kyx]);
    } else if (i < 221184) {
        int j = i - 73728;
        int oc = j/1152, k = j%1152, kyx = k >> 7, ic = k & 127;
        g_w3t[j] = __float2bfloat16_rn(cw3[oc*1152 + ic*9 + kyx]);
    } else if (i < 516096) {
        int j = i - 221184;
        int oc = j/1152, k = j%1152, kyx = k >> 7, ic = k & 127;
        g_w4t[j] = __float2bfloat16_rn(cw4[oc*1152 + ic*9 + kyx]);
    } else if (i < 1040384) {
        int j = i - 516096;
        g_wih2[j] = __float2bfloat16_rn(w_ih[(j >> 8)*322 + 66 + (j & 255)]);
    } else if (i < 2088960) {
        int j = i - 1040384;
        g_whh[j] = __float2bfloat16_rn(w_hh[(j >> 9)*512 + (j & 511)]);
    } else if (i < 2224128) {
        int j = i - 2088960;
        g_wT[j] = w_ih[(j & 2047)*322 + (j >> 11)];
    }
}

__global__ void conv1_kernel(const float* __restrict__ obs,
                             const float* __restrict__ w,
                             const float* __restrict__ bias) {
    __shared__ float img[784];
    __shared__ float pbuf[32*196];
    int b = blockIdx.x, tid = threadIdx.x;
    int warp = tid >> 5, lane = tid & 31;
    for (int i = tid; i < 784; i += 256) img[i] = obs[b*784 + i];
    __syncthreads();
    for (int half = 0; half < 2; half++) {
        #pragma unroll
        for (int ocl = 0; ocl < 4; ocl++) {
            int oc32 = warp*4 + ocl, oc = half*32 + oc32;
            float wv[9];
            #pragma unroll
            for (int j = 0; j < 9; j++) wv[j] = w[oc*9 + j];
            float bv = bias[oc];
            for (int idx = lane; idx < 196; idx += 32) {
                int py = idx/14, px = idx%14;
                float m = 0.f;
                #pragma unroll
                for (int dy = 0; dy < 3; dy++)
                    #pragma unroll
                    for (int dx = 0; dx < 3; dx++) {
                        int oy = 2*py + dy, ox = 2*px + dx;
                        float acc = bv;
                        #pragma unroll
                        for (int ky = 0; ky < 3; ky++) {
                            int iy = oy + ky - 2;
                            if (iy < 0 || iy >= 28) continue;
                            #pragma unroll
                            for (int kx = 0; kx < 3; kx++) {
                                int ix = ox + kx - 2;
                                if (ix < 0 || ix >= 28) continue;
                                acc += img[iy*28 + ix] * wv[ky*3 + kx];
                            }
                        }
                        m = fmaxf(m, fmaxf(acc, 0.f));
                    }
                pbuf[oc32*196 + idx] = m;
            }
        }
        __syncthreads();
        for (int i = tid; i < 32*196; i += 256) {
            int p = i >> 5, oc32 = i & 31;
            g_pool1[(b*196 + p)*64 + half*32 + oc32] = __float2bfloat16_rn(pbuf[oc32*196 + p]);
        }
        __syncthreads();
    }
}

#define STG 18432
#define GEMM_SMEM (6*STG)

// ---------------- conv GEMMs (modes 1,2,3) ----------------
template<int MODE>
__device__ __forceinline__ const bf16* weightB() {
    if constexpr (MODE == 1) return g_w2t;
    else if constexpr (MODE == 2) return g_w3t;
    else return g_w4t;
}

template<int MODE>
__device__ __forceinline__ void issue_conv(
        int it2, int nIter, int bb, int yy, int xx,
        const bf16* __restrict__ bptr, int gb, uint32_t aDst, uint32_t bDst) {
    if (it2 < nIter) {
        uint32_t so = (uint32_t)(it2 % 3) * STG;
        const bf16* sa; bool va = true;
        if constexpr (MODE == 1) {
            int ky = it2/3, kx = it2 - ky*3;
            int iy = yy + ky - 1, ix = xx + kx - 1;
            va = ((unsigned)iy < 14u) && ((unsigned)ix < 14u);
            int iyc = va ? iy : 0, ixc = va ? ix : 0;
            sa = g_pool1 + (bb*196 + iyc*14 + ixc)*64;
        } else if constexpr (MODE == 2) {
            int kyx = it2 >> 1; int ky = kyx/3, kx = kyx - ky*3;
            sa = g_pool2 + (bb*36 + (yy+ky)*6 + (xx+kx))*128 + (it2&1)*64;
        } else {
            int kyx = it2 >> 1; int ky = kyx/3, kx = kyx - ky*3;
            sa = g_conv3 + (bb*16 + (yy+ky)*4 + (xx+kx))*128 + (it2&1)*64;
        }
        const bf16* sb = bptr + it2*64;
        sa += gb*8; sb += gb*8;
        #pragma unroll
        for (int g = 0; g < 4; g++) {
            cp16(aDst + so + g*16, sa + g*8, va);
            cp16(bDst + so + g*16, sb + g*8, true);
        }
    }
    asm volatile("cp.async.commit_group;\n");
}

template<int MODE>
__global__ void __launch_bounds__(256) gemm_kernel(
        const float* __restrict__ bias, int K) {
    extern __shared__ __align__(16) char dsm[];
    uint32_t smBase = (uint32_t)__cvta_generic_to_shared(dsm);
    const int tid = threadIdx.x;
    const int m0 = blockIdx.x * 128;
    const int n0 = blockIdx.y * 128;

    const int rowS = tid >> 1;
    const int gb = (tid & 1) * 4;
    int bb = 0, yy = 0, xx = 0;
    {
        int m = m0 + rowS;
        if constexpr (MODE == 1) { bb = m/196; int p = m - bb*196; yy = p/14; xx = p - yy*14; }
        else if constexpr (MODE == 2) { bb = m >> 4; int p = m & 15; yy = p >> 2; xx = p & 3; }
        else { bb = m >> 2; int p = m & 3;  yy = p >> 1; xx = p & 1; }
    }
    constexpr int LDK = (MODE == 1) ? 576 : 1152;
    const bf16* bptr = weightB<MODE>() + (size_t)(n0 + rowS) * LDK;
    const uint32_t aDst = smBase + rowS*144 + gb*16;
    const uint32_t bDst = smBase + 3*STG + rowS*144 + gb*16;
    const int nIter = K >> 6;

    const int lane = tid & 31, warp = tid >> 5;
    const int wm = (warp & 3)*32, wn = (warp >> 2)*64;
    const int r = lane >> 2, kc2 = (lane & 3)*2;
    const int lrow = (lane & 7) + ((lane >> 3) & 1)*8;
    const int lgA  = (lane >> 4) & 1;
    const uint32_t offA0 = (uint32_t)((wm + lrow)*144 + lgA*16);
    const uint32_t offA1 = offA0 + 16*144;
    const int q = lane >> 3;
    const int brow = (lane & 7) + (q >> 1)*8;
    const int bgl  = q & 1;
    uint32_t offB[4];
    #pragma unroll
    for (int jp = 0; jp < 4; jp++)
        offB[jp] = (uint32_t)((wn + jp*16 + brow)*144 + bgl*16);

    float4 acc[2][8];
    #pragma unroll
    for (int mi = 0; mi < 2; mi++)
        #pragma unroll
        for (int j = 0; j < 8; j++) acc[mi][j] = make_float4(0.f, 0.f, 0.f, 0.f);

    issue_conv<MODE>(0, nIter, bb, yy, xx, bptr, gb, aDst, bDst);
    issue_conv<MODE>(1, nIter, bb, yy, xx, bptr, gb, aDst, bDst);

    int st = 0;
    for (int it = 0; it < nIter; it++) {
        asm volatile("cp.async.wait_group 1;\n");
        __syncthreads();
        issue_conv<MODE>(it + 2, nIter, bb, yy, xx, bptr, gb, aDst, bDst);
        uint32_t sA = smBase + (uint32_t)st*STG;
        uint32_t sB = sA + 3*STG;
        #pragma unroll
        for (int s = 0; s < 4; s++) {
            uint32_t a00, a01, a02, a03, a10, a11, a12, a13;
            ldsm4(a00, a01, a02, a03, sA + offA0 + s*32);
            ldsm4(a10, a11, a12, a13, sA + offA1 + s*32);
            #pragma unroll
            for (int jp = 0; jp < 4; jp++) {
                uint32_t b0, b1, b2, b3;
                ldsm4(b0, b1, b2, b3, sB + offB[jp] + s*32);
                mma16(acc[0][2*jp  ], a00, a01, a02, a03, b0, b1);
                mma16(acc[0][2*jp+1], a00, a01, a02, a03, b2, b3);
                mma16(acc[1][2*jp  ], a10, a11, a12, a13, b0, b1);
                mma16(acc[1][2*jp+1], a10, a11, a12, a13, b2, b3);
            }
        }
        st = (st == 2) ? 0 : st + 1;
        __syncthreads();
    }

    constexpr int LDO = (MODE == 3) ? 256 : 128;
    bf16* outp = (MODE == 1) ? g_conv2 : (MODE == 2) ? g_conv3 : g_conv4;
    #pragma unroll
    for (int mi = 0; mi < 2; mi++) {
        int row0 = m0 + wm + mi*16 + r, row1 = row0 + 8;
        #pragma unroll
        for (int j = 0; j < 8; j++) {
            int col = n0 + wn + j*8 + kc2;
            float b0 = bias[col], b1 = bias[col+1];
            float4 d = acc[mi][j];
            __nv_bfloat162 v0, v1;
            v0.x = __float2bfloat16_rn(fmaxf(d.x + b0, 0.f));
            v0.y = __float2bfloat16_rn(fmaxf(d.y + b1, 0.f));
            v1.x = __float2bfloat16_rn(fmaxf(d.z + b0, 0.f));
            v1.y = __float2bfloat16_rn(fmaxf(d.w + b1, 0.f));
            *(__nv_bfloat162*)&outp[row0*LDO + col] = v0;
            *(__nv_bfloat162*)&outp[row1*LDO + col] = v1;
        }
    }
}

__global__ void pool2_kernel() {
    int idx = blockIdx.x*256 + threadIdx.x;
    if (idx >= B_*36*128) return;
    int c = idx & 127, rr = idx >> 7;
    int p = rr % 36, b = rr / 36;
    int py = p / 6, px = p % 6;
    float m = 0.f;
    #pragma unroll
    for (int dy = 0; dy < 3; dy++)
        #pragma unroll
        for (int dx = 0; dx < 3; dx++)
            m = fmaxf(m, __bfloat162float(g_conv2[(b*196 + (2*py+dy)*14 + 2*px+dx)*128 + c]));
    g_pool2[idx] = __float2bfloat16_rn(m);
}

__global__ void pool4_kernel() {
    int idx = blockIdx.x*256 + threadIdx.x;
    if (idx >= B_*256) return;
    int c = idx & 255, b = idx >> 8;
    const bf16* p = g_conv4 + b*1024 + c;
    float m = fmaxf(fmaxf(__bfloat162float(p[0]), __bfloat162float(p[256])),
                    fmaxf(__bfloat162float(p[512]), __bfloat162float(p[768])));
    g_emb[idx] = __float2bfloat16_rn(m);
}

// ---------------- persistent LSTM ----------------
__device__ __forceinline__ void issue_lstm(int it2, int nIter,
        const bf16* __restrict__ aptr, const bf16* __restrict__ bptr,
        uint32_t aDst, uint32_t bDst) {
    if (it2 < nIter) {
        uint32_t so = (uint32_t)(it2 % 3) * STG;
        const bf16* sa = aptr + it2*64;
        const bf16* sb = bptr + it2*64;
        #pragma unroll
        for (int g = 0; g < 4; g++) {
            cp16(aDst + so + g*16, sa + g*8, true);
            cp16(bDst + so + g*16, sb + g*8, true);
        }
    }
    asm volatile("cp.async.commit_group;\n");
}

// MODE 0: embproj = emb @ wih2^T + b_ih + b_hh;  MODE 4: gates (with wT/embproj adds)
template<int MODE>
__device__ __forceinline__ void gemm_body(uint32_t smBase, int bid,
        const float* __restrict__ bias, const float* __restrict__ bias2,
        const int* __restrict__ ids, const int* __restrict__ oos, int t) {
    const int tid = threadIdx.x;
    const int m0 = (bid & 7) * 128, n0 = (bid >> 3) * 128;
    constexpr int LDK = (MODE == 0) ? 256 : 512;
    constexpr int nIter = LDK / 64;
    const int rowS = tid >> 1, gb = (tid & 1) * 4;
    const bf16* aptr = ((MODE == 0) ? g_emb : g_h) + (size_t)(m0 + rowS) * LDK + gb*8;
    const bf16* bptr = ((MODE == 0) ? g_wih2 : g_whh) + (size_t)(n0 + rowS) * LDK + gb*8;
    const uint32_t aDst = smBase + rowS*144 + gb*16;
    const uint32_t bDst = smBase + 3*STG + rowS*144 + gb*16;

    const int lane = tid & 31, warp = tid >> 5;
    const int wm = (warp & 3)*32, wn = (warp >> 2)*64;
    const int r = lane >> 2, kc2 = (lane & 3)*2;
    const int lrow = (lane & 7) + ((lane >> 3) & 1)*8;
    const int lgA = (lane >> 4) & 1;
    const uint32_t offA0 = (uint32_t)((wm + lrow)*144 + lgA*16);
    const uint32_t offA1 = offA0 + 16*144;
    const int q = lane >> 3;
    const int brow = (lane & 7) + (q >> 1)*8;
    const int bgl = q & 1;
    uint32_t offB[4];
    #pragma unroll
    for (int jp = 0; jp < 4; jp++)
        offB[jp] = (uint32_t)((wn + jp*16 + brow)*144 + bgl*16);

    float4 acc[2][8];
    #pragma unroll
    for (int mi = 0; mi < 2; mi++)
        #pragma unroll
        for (int j = 0; j < 8; j++) acc[mi][j] = make_float4(0.f, 0.f, 0.f, 0.f);

    issue_lstm(0, nIter, aptr, bptr, aDst, bDst);
    issue_lstm(1, nIter, aptr, bptr, aDst, bDst);
    int st = 0;
    for (int it = 0; it < nIter; it++) {
        asm volatile("cp.async.wait_group 1;\n");
        __syncthreads();
        issue_lstm(it + 2, nIter, aptr, bptr, aDst, bDst);
        uint32_t sA = smBase + (uint32_t)st*STG;
        uint32_t sB = sA + 3*STG;
        #pragma unroll
        for (int s = 0; s < 4; s++) {
            uint32_t a00, a01, a02, a03, a10, a11, a12, a13;
            ldsm4(a00, a01, a02, a03, sA + offA0 + s*32);
            ldsm4(a10, a11, a12, a13, sA + offA1 + s*32);
            #pragma unroll
            for (int jp = 0; jp < 4; jp++) {
                uint32_t b0, b1, b2, b3;
                ldsm4(b0, b1, b2, b3, sB + offB[jp] + s*32);
                mma16(acc[0][2*jp  ], a00, a01, a02, a03, b0, b1);
                mma16(acc[0][2*jp+1], a00, a01, a02, a03, b2, b3);
                mma16(acc[1][2*jp  ], a10, a11, a12, a13, b0, b1);
                mma16(acc[1][2*jp+1], a10, a11, a12, a13, b2, b3);
            }
        }
        st = (st == 2) ? 0 : st + 1;
        __syncthreads();
    }

    if constexpr (MODE == 0) {
        #pragma unroll
        for (int mi = 0; mi < 2; mi++) {
            int row0 = m0 + wm + mi*16 + r, row1 = row0 + 8;
            #pragma unroll
            for (int j = 0; j < 8; j++) {
                int col = n0 + wn + j*8 + kc2;
                float b0 = bias[col] + bias2[col], b1 = bias[col+1] + bias2[col+1];
                float4 d = acc[mi][j];
                *(float2*)&g_embproj[row0*2048 + col] = make_float2(d.x + b0, d.y + b1);
                *(float2*)&g_embproj[row1*2048 + col] = make_float2(d.z + b0, d.w + b1);
            }
        }
    } else {
        #pragma unroll
        for (int mi = 0; mi < 2; mi++) {
            int row0 = m0 + wm + mi*16 + r, row1 = row0 + 8;
            int id0 = ids[row0*10 + t - 1], oo0 = oos[row0*10 + t - 1];
            int id1 = ids[row1*10 + t - 1], oo1 = oos[row1*10 + t - 1];
            #pragma unroll
            for (int j = 0; j < 8; j++) {
                int col = n0 + wn + j*8 + kc2;
                float4 d = acc[mi][j];
                float2 e0 = *(const float2*)&g_embproj[row0*2048 + col];
                float2 wa0 = *(const float2*)&g_wT[id0*2048 + col];
                float2 wb0 = *(const float2*)&g_wT[(64 + oo0)*2048 + col];
                *(float2*)&g_gates[row0*2048 + col] =
                    make_float2(d.x + e0.x + wa0.x + wb0.x, d.y + e0.y + wa0.y + wb0.y);
                float2 e1 = *(const float2*)&g_embproj[row1*2048 + col];
                float2 wa1 = *(const float2*)&g_wT[id1*2048 + col];
                float2 wb1 = *(const float2*)&g_wT[(64 + oo1)*2048 + col];
                *(float2*)&g_gates[row1*2048 + col] =
                    make_float2(d.z + e1.x + wa1.x + wb1.x, d.w + e1.y + wa1.y + wb1.y);
            }
        }
    }
}

__global__ void __launch_bounds__(256) lstm_kernel(
        const float* __restrict__ b_ih, const float* __restrict__ b_hh,
        const int* __restrict__ ids, const int* __restrict__ oos,
        const float* __restrict__ lin_w, const float* __restrict__ lin_b,
        float* __restrict__ out) {
    extern __shared__ __align__(16) char dsm[];
    uint32_t smBase = (uint32_t)__cvta_generic_to_shared(dsm);
    float* hbuf = (float*)dsm;              // 8*512 floats
    float* lgbuf = hbuf + 8*512;            // 8*66 floats
    const int bid = blockIdx.x;
    const int tid = threadIdx.x;
    const int w = tid >> 5, lane = tid & 31;
    const int b0 = bid * 8;
    const int bw = b0 + w;
    float osum = 0.f;

    gemm_body<0>(smBase, bid, b_ih, b_hh, ids, oos, 0);
    gsync();

    for (int t = 0; t < T_; t++) {
        // cell for this block's 8 batches
        const float* gates = t ? g_gates : g_embproj;
        for (int idx = tid; idx < 8*512; idx += 256) {
            int b = b0 + (idx >> 9), j = idx & 511;
            const float* g = gates + b*2048;
            float ig = g[j], fg = g[j+512], gg = g[j+1024], og = g[j+1536];
            float cp = g_c[b*512 + j];
            float si = 1.f/(1.f + expf(-ig));
            float sf = 1.f/(1.f + expf(-fg));
            float so = 1.f/(1.f + expf(-og));
            float cc = sf*cp + si*tanhf(gg);
            g_c[b*512 + j] = cc;
            bf16 hb = __float2bfloat16_rn(so*tanhf(cc));
            g_h[b*512 + j] = hb;
            hbuf[idx] = __bfloat162float(hb);
        }
        __syncthreads();
        // logits: warp w -> batch bw
        {
            const float* hp = hbuf + w*512;
            float acc0 = lin_b[lane], acc1 = lin_b[lane+32];
            float acc2 = (lane < 2) ? lin_b[64+lane] : 0.f;
            const float* w0 = lin_w + lane*512;
            const float* w1 = lin_w + (lane+32)*512;
            const float* w2 = lin_w + (64+lane)*512;
            #pragma unroll 8
            for (int k = 0; k < 512; k++) {
                float hk = hp[k];
                acc0 += hk * w0[k];
                acc1 += hk * w1[k];
                if (lane < 2) acc2 += hk * w2[k];
            }
            float mx = fmaxf(acc0, acc1);
            #pragma unroll
            for (int o = 16; o > 0; o >>= 1) mx = fmaxf(mx, __shfl_xor_sync(0xffffffffu, mx, o));
            float s = expf(acc0 - mx) + expf(acc1 - mx);
            #pragma unroll
            for (int o = 16; o > 0; o >>= 1) s += __shfl_xor_sync(0xffffffffu, s, o);
            float* lw = lgbuf + w*66;
            lw[lane] = acc0; lw[lane+32] = acc1;
            float a0 = __shfl_sync(0xffffffffu, acc2, 0);
            float a1 = __shfl_sync(0xffffffffu, acc2, 1);
            __syncwarp();
            if (lane == 0) {
                int idt = ids[bw*10 + t], oot = oos[bw*10 + t];
                float lp_id = lw[idt] - mx - logf(s);
                float mo = fmaxf(a0, a1);
                float ls = mo + logf(expf(a0 - mo) + expf(a1 - mo));
                float lp_oo = (oot ? a1 : a0) - ls;
                osum += lp_id + (t > 0 ? lp_oo : 0.f);
            }
        }
        if (t < T_ - 1) {
            gsync();
            gemm_body<4>(smBase, bid, nullptr, nullptr, ids, oos, t + 1);
            gsync();
        }
    }
    if (lane == 0) out[bw] = osum;
}

extern "C" void kernel_launch(void* const* d_in, const int* in_sizes, int n_in,
                              void* d_out, int out_size) {
    const float* obs  = (const float*)d_in[0];
    const int*   ids  = (const int*)  d_in[1];
    const int*   oos  = (const int*)  d_in[2];
    const float* cw1  = (const float*)d_in[3];
    const float* cb1  = (const float*)d_in[4];
    const float* cw2  = (const float*)d_in[5];
    const float* cb2  = (const float*)d_in[6];
    const float* cw3  = (const float*)d_in[7];
    const float* cb3  = (const float*)d_in[8];
    const float* cw4  = (const float*)d_in[9];
    const float* cb4  = (const float*)d_in[10];
    const float* w_ih = (const float*)d_in[11];
    const float* w_hh = (const float*)d_in[12];
    const float* b_ih = (const float*)d_in[13];
    const float* b_hh = (const float*)d_in[14];
    const float* lin_w= (const float*)d_in[15];
    const float* lin_b= (const float*)d_in[16];
    float* out = (float*)d_out;

    cudaFuncSetAttribute(gemm_kernel<1>, cudaFuncAttributeMaxDynamicSharedMemorySize, GEMM_SMEM);
    cudaFuncSetAttribute(gemm_kernel<2>, cudaFuncAttributeMaxDynamicSharedMemorySize, GEMM_SMEM);
    cudaFuncSetAttribute(gemm_kernel<3>, cudaFuncAttributeMaxDynamicSharedMemorySize, GEMM_SMEM);
    cudaFuncSetAttribute(lstm_kernel,    cudaFuncAttributeMaxDynamicSharedMemorySize, GEMM_SMEM);

    init_kernel<<<(B_*H_ + 255)/256, 256>>>();
    prep_kernel<<<(2224128 + 255)/256, 256>>>(cw2, cw3, cw4, w_ih, w_hh);
    conv1_kernel<<<B_, 256>>>(obs, cw1, cb1);
    gemm_kernel<1><<<dim3(1568, 1), 256, GEMM_SMEM>>>(cb2, 576);
    pool2_kernel<<<(B_*36*128 + 255)/256, 256>>>();
    gemm_kernel<2><<<dim3(128, 1), 256, GEMM_SMEM>>>(cb3, 1152);
    gemm_kernel<3><<<dim3(32, 2), 256, GEMM_SMEM>>>(cb4, 1152);
    pool4_kernel<<<(B_*256 + 255)/256, 256>>>();
    lstm_kernel<<<128, 256, GEMM_SMEM>>>(b_ih, b_hh, ids, oos, lin_w, lin_b, out);
}

// round 16
// speedup vs baseline: 1.0423x; 1.0423x over previous
#include <cuda_runtime.h>
#include <cuda_bf16.h>
#include <cstdint>
#include <math.h>

#define B_ 1024
#define H_ 512
#define T_ 10

typedef __nv_bfloat16 bf16;

__device__ bf16  g_pool1[B_*196*64];
__device__ bf16  g_conv2[B_*196*128];
__device__ bf16  g_pool2[B_*36*128];
__device__ bf16  g_conv3[B_*16*128];
__device__ bf16  g_conv4[B_*4*256];
__device__ bf16  g_emb[B_*256];
__device__ float g_embproj[B_*2048];
__device__ bf16  g_h[B_*H_];
__device__ float g_c[B_*H_];
__device__ float g_gates[B_*2048];
__device__ float g_wT[66*2048];
__device__ bf16  g_w2t[128*576];
__device__ bf16  g_w3t[128*1152];
__device__ bf16  g_w4t[256*1152];
__device__ bf16  g_wih2[2048*256];
__device__ bf16  g_whh[2048*512];

__device__ __forceinline__ void mma16(float4& d, uint32_t a0, uint32_t a1,
        uint32_t a2, uint32_t a3, uint32_t b0, uint32_t b1) {
    asm volatile(
        "mma.sync.aligned.m16n8k16.row.col.f32.bf16.bf16.f32 "
        "{%0,%1,%2,%3}, {%4,%5,%6,%7}, {%8,%9}, {%0,%1,%2,%3};\n"
        : "+f"(d.x), "+f"(d.y), "+f"(d.z), "+f"(d.w)
        : "r"(a0), "r"(a1), "r"(a2), "r"(a3), "r"(b0), "r"(b1));
}
__device__ __forceinline__ void ldsm4(uint32_t& r0, uint32_t& r1,
        uint32_t& r2, uint32_t& r3, uint32_t addr) {
    asm volatile("ldmatrix.sync.aligned.m8n8.x4.shared.b16 {%0,%1,%2,%3}, [%4];"
                 : "=r"(r0), "=r"(r1), "=r"(r2), "=r"(r3) : "r"(addr));
}
__device__ __forceinline__ void cp16(uint32_t dst, const void* src, bool v) {
    int sz = v ? 16 : 0;
    asm volatile("cp.async.cg.shared.global [%0], [%1], 16, %2;\n"
                 :: "r"(dst), "l"(src), "r"(sz));
}
__device__ __forceinline__ float tanha(float x) {
    float y;
    asm("tanh.approx.f32 %0, %1;" : "=f"(y) : "f"(x));
    return y;
}

__global__ void init_kernel(float* __restrict__ out) {
    int idx = blockIdx.x*256 + threadIdx.x;
    if (idx < B_*H_) g_c[idx] = 0.f;
    if (idx < B_)    out[idx] = 0.f;
}

__global__ void prep_kernel(const float* __restrict__ cw2,
                            const float* __restrict__ cw3,
                            const float* __restrict__ cw4,
                            const float* __restrict__ w_ih,
                            const float* __restrict__ w_hh) {
    int i = blockIdx.x*256 + threadIdx.x;
    if (i < 73728) {
        int oc = i/576, k = i%576, kyx = k >> 6, ic = k & 63;
        g_w2t[i] = __float2bfloat16_rn(cw2[oc*576 + ic*9 + kyx]);
    } else if (i < 221184) {
        int j = i - 73728;
        int oc = j/1152, k = j%1152, kyx = k >> 7, ic = k & 127;
        g_w3t[j] = __float2bfloat16_rn(cw3[oc*1152 + ic*9 + kyx]);
    } else if (i < 516096) {
        int j = i - 221184;
        int oc = j/1152, k = j%1152, kyx = k >> 7, ic = k & 127;
        g_w4t[j] = __float2bfloat16_rn(cw4[oc*1152 + ic*9 + kyx]);
    } else if (i < 1040384) {
        int j = i - 516096;
        g_wih2[j] = __float2bfloat16_rn(w_ih[(j >> 8)*322 + 66 + (j & 255)]);
    } else if (i < 2088960) {
        int j = i - 1040384;
        g_whh[j] = __float2bfloat16_rn(w_hh[(j >> 9)*512 + (j & 511)]);
    } else if (i < 2224128) {
        int j = i - 2088960;
        g_wT[j] = w_ih[(j & 2047)*322 + (j >> 11)];
    }
}

__global__ void conv1_kernel(const float* __restrict__ obs,
                             const float* __restrict__ w,
                             const float* __restrict__ bias) {
    __shared__ float img[784];
    __shared__ float pbuf[32*196];
    int b = blockIdx.x, tid = threadIdx.x;
    int warp = tid >> 5, lane = tid & 31;
    for (int i = tid; i < 784; i += 256) img[i] = obs[b*784 + i];
    __syncthreads();
    for (int half = 0; half < 2; half++) {
        #pragma unroll
        for (int ocl = 0; ocl < 4; ocl++) {
            int oc32 = warp*4 + ocl, oc = half*32 + oc32;
            float wv[9];
            #pragma unroll
            for (int j = 0; j < 9; j++) wv[j] = w[oc*9 + j];
            float bv = bias[oc];
            for (int idx = lane; idx < 196; idx += 32) {
                int py = idx/14, px = idx%14;
                float m = 0.f;
                #pragma unroll
                for (int dy = 0; dy < 3; dy++)
                    #pragma unroll
                    for (int dx = 0; dx < 3; dx++) {
                        int oy = 2*py + dy, ox = 2*px + dx;
                        float acc = bv;
                        #pragma unroll
                        for (int ky = 0; ky < 3; ky++) {
                            int iy = oy + ky - 2;
                            if (iy < 0 || iy >= 28) continue;
                            #pragma unroll
                            for (int kx = 0; kx < 3; kx++) {
                                int ix = ox + kx - 2;
                                if (ix < 0 || ix >= 28) continue;
                                acc += img[iy*28 + ix] * wv[ky*3 + kx];
                            }
                        }
                        m = fmaxf(m, fmaxf(acc, 0.f));
                    }
                pbuf[oc32*196 + idx] = m;
            }
        }
        __syncthreads();
        for (int i = tid; i < 32*196; i += 256) {
            int p = i >> 5, oc32 = i & 31;
            g_pool1[(b*196 + p)*64 + half*32 + oc32] = __float2bfloat16_rn(pbuf[oc32*196 + p]);
        }
        __syncthreads();
    }
}

#define STG 18432
#define GEMM_SMEM (6*STG)

template<int MODE>
__device__ __forceinline__ const bf16* weightB() {
    if constexpr (MODE == 0) return g_wih2;
    else if constexpr (MODE == 1) return g_w2t;
    else if constexpr (MODE == 2) return g_w3t;
    else if constexpr (MODE == 3) return g_w4t;
    else return g_whh;
}

template<int MODE>
__device__ __forceinline__ void issue_stage(
        int it2, int nIter, int bb, int yy, int xx,
        const bf16* __restrict__ bptr, int gb, uint32_t aDst, uint32_t bDst) {
    if (it2 < nIter) {
        uint32_t so = (uint32_t)(it2 % 3) * STG;
        const bf16* sa; bool va = true;
        if constexpr (MODE == 0)      sa = g_emb + bb*256 + it2*64;
        else if constexpr (MODE == 4) sa = g_h   + bb*512 + it2*64;
        else if constexpr (MODE == 1) {
            int ky = it2/3, kx = it2 - ky*3;
            int iy = yy + ky - 1, ix = xx + kx - 1;
            va = ((unsigned)iy < 14u) && ((unsigned)ix < 14u);
            int iyc = va ? iy : 0, ixc = va ? ix : 0;
            sa = g_pool1 + (bb*196 + iyc*14 + ixc)*64;
        } else if constexpr (MODE == 2) {
            int kyx = it2 >> 1; int ky = kyx/3, kx = kyx - ky*3;
            sa = g_pool2 + (bb*36 + (yy+ky)*6 + (xx+kx))*128 + (it2&1)*64;
        } else {
            int kyx = it2 >> 1; int ky = kyx/3, kx = kyx - ky*3;
            sa = g_conv3 + (bb*16 + (yy+ky)*4 + (xx+kx))*128 + (it2&1)*64;
        }
        const bf16* sb = bptr + it2*64;
        sa += gb*8; sb += gb*8;
        #pragma unroll
        for (int g = 0; g < 4; g++) {
            cp16(aDst + so + g*16, sa + g*8, va);
            cp16(bDst + so + g*16, sb + g*8, true);
        }
    }
    asm volatile("cp.async.commit_group;\n");
}

template<int MODE>
__global__ void __launch_bounds__(256) gemm_kernel(
        const float* __restrict__ bias,
        const float* __restrict__ bias2,
        const int* __restrict__ ids,
        const int* __restrict__ oos,
        int K, int t) {
    extern __shared__ __align__(16) char dsm[];
    uint32_t smBase = (uint32_t)__cvta_generic_to_shared(dsm);
    const int tid = threadIdx.x;
    const int m0 = blockIdx.x * 128;
    const int n0 = blockIdx.y * 128;

    const int rowS = tid >> 1;
    const int gb = (tid & 1) * 4;
    int bb = 0, yy = 0, xx = 0;
    {
        int m = m0 + rowS;
        if constexpr (MODE == 1) { bb = m/196; int p = m - bb*196; yy = p/14; xx = p - yy*14; }
        else if constexpr (MODE == 2) { bb = m >> 4; int p = m & 15; yy = p >> 2; xx = p & 3; }
        else if constexpr (MODE == 3) { bb = m >> 2; int p = m & 3;  yy = p >> 1; xx = p & 1; }
        else { bb = m; }
    }
    constexpr int LDK = (MODE == 0) ? 256 : (MODE == 4) ? 512 : (MODE == 1) ? 576 : 1152;
    const bf16* bptr = weightB<MODE>() + (size_t)(n0 + rowS) * LDK;
    const uint32_t aDst = smBase + rowS*144 + gb*16;
    const uint32_t bDst = smBase + 3*STG + rowS*144 + gb*16;

    const int nIter = K >> 6;

    const int lane = tid & 31, warp = tid >> 5;
    const int wm = (warp & 3)*32, wn = (warp >> 2)*64;
    const int r = lane >> 2, kc2 = (lane & 3)*2;
    const int lrow = (lane & 7) + ((lane >> 3) & 1)*8;
    const int lgA  = (lane >> 4) & 1;
    const uint32_t offA0 = (uint32_t)((wm + lrow)*144 + lgA*16);
    const uint32_t offA1 = offA0 + 16*144;
    const int q = lane >> 3;
    const int brow = (lane & 7) + (q >> 1)*8;
    const int bgl  = q & 1;
    uint32_t offB[4];
    #pragma unroll
    for (int jp = 0; jp < 4; jp++)
        offB[jp] = (uint32_t)((wn + jp*16 + brow)*144 + bgl*16);

    float4 acc[2][8];
    #pragma unroll
    for (int mi = 0; mi < 2; mi++)
        #pragma unroll
        for (int j = 0; j < 8; j++) acc[mi][j] = make_float4(0.f, 0.f, 0.f, 0.f);

    issue_stage<MODE>(0, nIter, bb, yy, xx, bptr, gb, aDst, bDst);
    issue_stage<MODE>(1, nIter, bb, yy, xx, bptr, gb, aDst, bDst);

    int st = 0;
    for (int it = 0; it < nIter; it++) {
        asm volatile("cp.async.wait_group 1;\n");
        __syncthreads();
        issue_stage<MODE>(it + 2, nIter, bb, yy, xx, bptr, gb, aDst, bDst);
        uint32_t sA = smBase + (uint32_t)st*STG;
        uint32_t sB = sA + 3*STG;
        #pragma unroll
        for (int s = 0; s < 4; s++) {
            uint32_t a00, a01, a02, a03, a10, a11, a12, a13;
            ldsm4(a00, a01, a02, a03, sA + offA0 + s*32);
            ldsm4(a10, a11, a12, a13, sA + offA1 + s*32);
            #pragma unroll
            for (int jp = 0; jp < 4; jp++) {
                uint32_t b0, b1, b2, b3;
                ldsm4(b0, b1, b2, b3, sB + offB[jp] + s*32);
                mma16(acc[0][2*jp  ], a00, a01, a02, a03, b0, b1);
                mma16(acc[0][2*jp+1], a00, a01, a02, a03, b2, b3);
                mma16(acc[1][2*jp  ], a10, a11, a12, a13, b0, b1);
                mma16(acc[1][2*jp+1], a10, a11, a12, a13, b2, b3);
            }
        }
        st = (st == 2) ? 0 : st + 1;
    }

    if constexpr (MODE == 4) {
        #pragma unroll
        for (int mi = 0; mi < 2; mi++) {
            int row0 = m0 + wm + mi*16 + r, row1 = row0 + 8;
            int id0 = ids[row0*10 + t - 1], oo0 = oos[row0*10 + t - 1];
            int id1 = ids[row1*10 + t - 1], oo1 = oos[row1*10 + t - 1];
            #pragma unroll
            for (int j = 0; j < 8; j++) {
                int col = n0 + wn + j*8 + kc2;
                float4 d = acc[mi][j];
                float2 e0 = *(const float2*)&g_embproj[row0*2048 + col];
                float2 wa0 = *(const float2*)&g_wT[id0*2048 + col];
                float2 wb0 = *(const float2*)&g_wT[(64 + oo0)*2048 + col];
                *(float2*)&g_gates[row0*2048 + col] =
                    make_float2(d.x + e0.x + wa0.x + wb0.x, d.y + e0.y + wa0.y + wb0.y);
                float2 e1 = *(const float2*)&g_embproj[row1*2048 + col];
                float2 wa1 = *(const float2*)&g_wT[id1*2048 + col];
                float2 wb1 = *(const float2*)&g_wT[(64 + oo1)*2048 + col];
                *(float2*)&g_gates[row1*2048 + col] =
                    make_float2(d.z + e1.x + wa1.x + wb1.x, d.w + e1.y + wa1.y + wb1.y);
            }
        }
    } else if constexpr (MODE == 0) {
        #pragma unroll
        for (int mi = 0; mi < 2; mi++) {
            int row0 = m0 + wm + mi*16 + r, row1 = row0 + 8;
            #pragma unroll
            for (int j = 0; j < 8; j++) {
                int col = n0 + wn + j*8 + kc2;
                float b0 = bias[col] + bias2[col], b1 = bias[col+1] + bias2[col+1];
                float4 d = acc[mi][j];
                *(float2*)&g_embproj[row0*2048 + col] = make_float2(d.x + b0, d.y + b1);
                *(float2*)&g_embproj[row1*2048 + col] = make_float2(d.z + b0, d.w + b1);
            }
        }
    } else {
        constexpr int LDO = (MODE == 3) ? 256 : 128;
        bf16* outp = (MODE == 1) ? g_conv2 : (MODE == 2) ? g_conv3 : g_conv4;
        #pragma unroll
        for (int mi = 0; mi < 2; mi++) {
            int row0 = m0 + wm + mi*16 + r, row1 = row0 + 8;
            #pragma unroll
            for (int j = 0; j < 8; j++) {
                int col = n0 + wn + j*8 + kc2;
                float b0 = bias[col], b1 = bias[col+1];
                float4 d = acc[mi][j];
                __nv_bfloat162 v0, v1;
                v0.x = __float2bfloat16_rn(fmaxf(d.x + b0, 0.f));
                v0.y = __float2bfloat16_rn(fmaxf(d.y + b1, 0.f));
                v1.x = __float2bfloat16_rn(fmaxf(d.z + b0, 0.f));
                v1.y = __float2bfloat16_rn(fmaxf(d.w + b1, 0.f));
                *(__nv_bfloat162*)&outp[row0*LDO + col] = v0;
                *(__nv_bfloat162*)&outp[row1*LDO + col] = v1;
            }
        }
    }
}

__global__ void pool2_kernel() {
    int idx = blockIdx.x*256 + threadIdx.x;
    if (idx >= B_*36*128) return;
    int c = idx & 127, rr = idx >> 7;
    int p = rr % 36, b = rr / 36;
    int py = p / 6, px = p % 6;
    float m = 0.f;
    #pragma unroll
    for (int dy = 0; dy < 3; dy++)
        #pragma unroll
        for (int dx = 0; dx < 3; dx++)
            m = fmaxf(m, __bfloat162float(g_conv2[(b*196 + (2*py+dy)*14 + 2*px+dx)*128 + c]));
    g_pool2[idx] = __float2bfloat16_rn(m);
}

__global__ void pool4_kernel() {
    int idx = blockIdx.x*256 + threadIdx.x;
    if (idx >= B_*256) return;
    int c = idx & 255, b = idx >> 8;
    const bf16* p = g_conv4 + b*1024 + c;
    float m = fmaxf(fmaxf(__bfloat162float(p[0]), __bfloat162float(p[256])),
                    fmaxf(__bfloat162float(p[512]), __bfloat162float(p[768])));
    g_emb[idx] = __float2bfloat16_rn(m);
}

// ---- fused cell + logits: grid 128, block 256, warp-per-batch ----
__global__ void __launch_bounds__(256) cellog_kernel(
        const int* __restrict__ ids, const int* __restrict__ oos,
        const float* __restrict__ lin_w, const float* __restrict__ lin_b,
        float* __restrict__ out, int t) {
    __shared__ float hbuf[8*512];
    __shared__ float lgbuf[8*64];
    const int bid = blockIdx.x, tid = threadIdx.x;
    const int w = tid >> 5, lane = tid & 31;
    const int b0 = bid * 8, bw = b0 + w;
    const float* gates = t ? g_gates : g_embproj;
    for (int idx = tid; idx < 8*512; idx += 256) {
        int b = b0 + (idx >> 9), j = idx & 511;
        const float* g = gates + b*2048;
        float ig = g[j], fg = g[j+512], gg = g[j+1024], og = g[j+1536];
        float cp = g_c[b*512 + j];
        float si = 0.5f + 0.5f*tanha(0.5f*ig);
        float sf = 0.5f + 0.5f*tanha(0.5f*fg);
        float so = 0.5f + 0.5f*tanha(0.5f*og);
        float cc = sf*cp + si*tanha(gg);
        g_c[b*512 + j] = cc;
        bf16 hb = __float2bfloat16_rn(so*tanha(cc));
        g_h[b*512 + j] = hb;
        hbuf[idx] = __bfloat162float(hb);
    }
    __syncthreads();
    const float* hp = hbuf + w*512;
    float acc0 = lin_b[lane], acc1 = lin_b[lane+32];
    float acc2 = (lane < 2) ? lin_b[64+lane] : 0.f;
    const float* w0 = lin_w + lane*512;
    const float* w1 = lin_w + (lane+32)*512;
    const float* w2 = lin_w + (64+lane)*512;
    #pragma unroll 8
    for (int k = 0; k < 512; k++) {
        float hk = hp[k];
        acc0 += hk * w0[k];
        acc1 += hk * w1[k];
        if (lane < 2) acc2 += hk * w2[k];
    }
    float mx = fmaxf(acc0, acc1);
    #pragma unroll
    for (int o = 16; o > 0; o >>= 1) mx = fmaxf(mx, __shfl_xor_sync(0xffffffffu, mx, o));
    float s = expf(acc0 - mx) + expf(acc1 - mx);
    #pragma unroll
    for (int o = 16; o > 0; o >>= 1) s += __shfl_xor_sync(0xffffffffu, s, o);
    float* lw = lgbuf + w*64;
    lw[lane] = acc0; lw[lane+32] = acc1;
    float a0 = __shfl_sync(0xffffffffu, acc2, 0);
    float a1 = __shfl_sync(0xffffffffu, acc2, 1);
    __syncwarp();
    if (lane == 0) {
        int idt = ids[bw*10 + t], oot = oos[bw*10 + t];
        float lp_id = lw[idt] - mx - logf(s);
        float mo = fmaxf(a0, a1);
        float ls = mo + logf(expf(a0 - mo) + expf(a1 - mo));
        float lp_oo = (oot ? a1 : a0) - ls;
        out[bw] += lp_id + (t > 0 ? lp_oo : 0.f);
    }
}

extern "C" void kernel_launch(void* const* d_in, const int* in_sizes, int n_in,
                              void* d_out, int out_size) {
    const float* obs  = (const float*)d_in[0];
    const int*   ids  = (const int*)  d_in[1];
    const int*   oos  = (const int*)  d_in[2];
    const float* cw1  = (const float*)d_in[3];
    const float* cb1  = (const float*)d_in[4];
    const float* cw2  = (const float*)d_in[5];
    const float* cb2  = (const float*)d_in[6];
    const float* cw3  = (const float*)d_in[7];
    const float* cb3  = (const float*)d_in[8];
    const float* cw4  = (const float*)d_in[9];
    const float* cb4  = (const float*)d_in[10];
    const float* w_ih = (const float*)d_in[11];
    const float* w_hh = (const float*)d_in[12];
    const float* b_ih = (const float*)d_in[13];
    const float* b_hh = (const float*)d_in[14];
    const float* lin_w= (const float*)d_in[15];
    const float* lin_b= (const float*)d_in[16];
    float* out = (float*)d_out;

    cudaFuncSetAttribute(gemm_kernel<0>, cudaFuncAttributeMaxDynamicSharedMemorySize, GEMM_SMEM);
    cudaFuncSetAttribute(gemm_kernel<1>, cudaFuncAttributeMaxDynamicSharedMemorySize, GEMM_SMEM);
    cudaFuncSetAttribute(gemm_kernel<2>, cudaFuncAttributeMaxDynamicSharedMemorySize, GEMM_SMEM);
    cudaFuncSetAttribute(gemm_kernel<3>, cudaFuncAttributeMaxDynamicSharedMemorySize, GEMM_SMEM);
    cudaFuncSetAttribute(gemm_kernel<4>, cudaFuncAttributeMaxDynamicSharedMemorySize, GEMM_SMEM);

    init_kernel<<<(B_*H_ + 255)/256, 256>>>(out);
    prep_kernel<<<(2224128 + 255)/256, 256>>>(cw2, cw3, cw4, w_ih, w_hh);
    conv1_kernel<<<B_, 256>>>(obs, cw1, cb1);
    gemm_kernel<1><<<dim3(1568, 1), 256, GEMM_SMEM>>>(cb2, nullptr, nullptr, nullptr, 576, 0);
    pool2_kernel<<<(B_*36*128 + 255)/256, 256>>>();
    gemm_kernel<2><<<dim3(128, 1), 256, GEMM_SMEM>>>(cb3, nullptr, nullptr, nullptr, 1152, 0);
    gemm_kernel<3><<<dim3(32, 2), 256, GEMM_SMEM>>>(cb4, nullptr, nullptr, nullptr, 1152, 0);
    pool4_kernel<<<(B_*256 + 255)/256, 256>>>();
    gemm_kernel<0><<<dim3(8, 16), 256, GEMM_SMEM>>>(b_ih, b_hh, nullptr, nullptr, 256, 0);
    cellog_kernel<<<128, 256>>>(ids, oos, lin_w, lin_b, out, 0);
    for (int t = 1; t < T_; t++) {
        gemm_kernel<4><<<dim3(8, 16), 256, GEMM_SMEM>>>(nullptr, nullptr, ids, oos, 512, t);
        cellog_kernel<<<128, 256>>>(ids, oos, lin_w, lin_b, out, t);
    }
}

// round 17
// speedup vs baseline: 2.8813x; 2.7644x over previous
#include <cuda_runtime.h>
#include <cuda_bf16.h>
#include <cstdint>
#include <math.h>

#define B_ 1024
#define H_ 512
#define T_ 10

typedef __nv_bfloat16 bf16;

__device__ bf16  g_pool1[B_*196*64];
__device__ bf16  g_conv2[B_*196*128];
__device__ bf16  g_pool2[B_*36*128];
__device__ bf16  g_conv3[B_*16*128];
__device__ bf16  g_conv4[B_*4*256];
__device__ bf16  g_emb[B_*256];
__device__ float g_embproj[B_*2048];
__device__ bf16  g_h[B_*H_];
__device__ float g_c[B_*H_];
__device__ float g_gates[B_*2048];
__device__ float g_logits[B_*128];
__device__ float g_wT[66*2048];
__device__ bf16  g_w2t[128*576];
__device__ bf16  g_w3t[128*1152];
__device__ bf16  g_w4t[256*1152];
__device__ bf16  g_wih2[2048*256];
__device__ bf16  g_whh[2176*512];   // rows 0..2047 = w_hh, 2048..2113 = lin_w, rest zero

__device__ __forceinline__ void mma16(float4& d, uint32_t a0, uint32_t a1,
        uint32_t a2, uint32_t a3, uint32_t b0, uint32_t b1) {
    asm volatile(
        "mma.sync.aligned.m16n8k16.row.col.f32.bf16.bf16.f32 "
        "{%0,%1,%2,%3}, {%4,%5,%6,%7}, {%8,%9}, {%0,%1,%2,%3};\n"
        : "+f"(d.x), "+f"(d.y), "+f"(d.z), "+f"(d.w)
        : "r"(a0), "r"(a1), "r"(a2), "r"(a3), "r"(b0), "r"(b1));
}
__device__ __forceinline__ void ldsm4(uint32_t& r0, uint32_t& r1,
        uint32_t& r2, uint32_t& r3, uint32_t addr) {
    asm volatile("ldmatrix.sync.aligned.m8n8.x4.shared.b16 {%0,%1,%2,%3}, [%4];"
                 : "=r"(r0), "=r"(r1), "=r"(r2), "=r"(r3) : "r"(addr));
}
__device__ __forceinline__ void cp16(uint32_t dst, const void* src, bool v) {
    int sz = v ? 16 : 0;
    asm volatile("cp.async.cg.shared.global [%0], [%1], 16, %2;\n"
                 :: "r"(dst), "l"(src), "r"(sz));
}
__device__ __forceinline__ float tanha(float x) {
    float y;
    asm("tanh.approx.f32 %0, %1;" : "=f"(y) : "f"(x));
    return y;
}

__global__ void init_kernel(float* __restrict__ out) {
    int idx = blockIdx.x*256 + threadIdx.x;
    if (idx < B_*H_) g_c[idx] = 0.f;
    if (idx < B_)    out[idx] = 0.f;
}

__global__ void prep_kernel(const float* __restrict__ cw2,
                            const float* __restrict__ cw3,
                            const float* __restrict__ cw4,
                            const float* __restrict__ w_ih,
                            const float* __restrict__ w_hh,
                            const float* __restrict__ lin_w) {
    int i = blockIdx.x*256 + threadIdx.x;
    if (i < 73728) {
        int oc = i/576, k = i%576, kyx = k >> 6, ic = k & 63;
        g_w2t[i] = __float2bfloat16_rn(cw2[oc*576 + ic*9 + kyx]);
    } else if (i < 221184) {
        int j = i - 73728;
        int oc = j/1152, k = j%1152, kyx = k >> 7, ic = k & 127;
        g_w3t[j] = __float2bfloat16_rn(cw3[oc*1152 + ic*9 + kyx]);
    } else if (i < 516096) {
        int j = i - 221184;
        int oc = j/1152, k = j%1152, kyx = k >> 7, ic = k & 127;
        g_w4t[j] = __float2bfloat16_rn(cw4[oc*1152 + ic*9 + kyx]);
    } else if (i < 1040384) {
        int j = i - 516096;
        g_wih2[j] = __float2bfloat16_rn(w_ih[(j >> 8)*322 + 66 + (j & 255)]);
    } else if (i < 2088960) {
        int j = i - 1040384;
        g_whh[j] = __float2bfloat16_rn(w_hh[(j >> 9)*512 + (j & 511)]);
    } else if (i < 2224128) {
        int j = i - 2088960;
        g_wT[j] = w_ih[(j & 2047)*322 + (j >> 11)];
    } else if (i < 2257920) {
        int j = i - 2224128;
        int rr = j >> 9, k = j & 511;
        g_whh[(2048 + rr)*512 + k] = __float2bfloat16_rn(lin_w[rr*512 + k]);
    }
}

__global__ void conv1_kernel(const float* __restrict__ obs,
                             const float* __restrict__ w,
                             const float* __restrict__ bias) {
    __shared__ float img[784];
    __shared__ float pbuf[32*196];
    int b = blockIdx.x, tid = threadIdx.x;
    int warp = tid >> 5, lane = tid & 31;
    for (int i = tid; i < 784; i += 256) img[i] = obs[b*784 + i];
    __syncthreads();
    for (int half = 0; half < 2; half++) {
        #pragma unroll
        for (int ocl = 0; ocl < 4; ocl++) {
            int oc32 = warp*4 + ocl, oc = half*32 + oc32;
            float wv[9];
            #pragma unroll
            for (int j = 0; j < 9; j++) wv[j] = w[oc*9 + j];
            float bv = bias[oc];
            for (int idx = lane; idx < 196; idx += 32) {
                int py = idx/14, px = idx%14;
                float m = 0.f;
                #pragma unroll
                for (int dy = 0; dy < 3; dy++)
                    #pragma unroll
                    for (int dx = 0; dx < 3; dx++) {
                        int oy = 2*py + dy, ox = 2*px + dx;
                        float acc = bv;
                        #pragma unroll
                        for (int ky = 0; ky < 3; ky++) {
                            int iy = oy + ky - 2;
                            if (iy < 0 || iy >= 28) continue;
                            #pragma unroll
                            for (int kx = 0; kx < 3; kx++) {
                                int ix = ox + kx - 2;
                                if (ix < 0 || ix >= 28) continue;
                                acc += img[iy*28 + ix] * wv[ky*3 + kx];
                            }
                        }
                        m = fmaxf(m, fmaxf(acc, 0.f));
                    }
                pbuf[oc32*196 + idx] = m;
            }
        }
        __syncthreads();
        for (int i = tid; i < 32*196; i += 256) {
            int p = i >> 5, oc32 = i & 31;
            g_pool1[(b*196 + p)*64 + half*32 + oc32] = __float2bfloat16_rn(pbuf[oc32*196 + p]);
        }
        __syncthreads();
    }
}

#define STG 18432
#define GEMM_SMEM (6*STG)

template<int MODE>
__device__ __forceinline__ const bf16* weightB() {
    if constexpr (MODE == 0) return g_wih2;
    else if constexpr (MODE == 1) return g_w2t;
    else if constexpr (MODE == 2) return g_w3t;
    else if constexpr (MODE == 3) return g_w4t;
    else return g_whh;
}

template<int MODE>
__device__ __forceinline__ void issue_stage(
        int it2, int nIter, int bb, int yy, int xx,
        const bf16* __restrict__ bptr, int gb, uint32_t aDst, uint32_t bDst) {
    if (it2 < nIter) {
        uint32_t so = (uint32_t)(it2 % 3) * STG;
        const bf16* sa; bool va = true;
        if constexpr (MODE == 0)      sa = g_emb + bb*256 + it2*64;
        else if constexpr (MODE == 4) sa = g_h   + bb*512 + it2*64;
        else if constexpr (MODE == 1) {
            int ky = it2/3, kx = it2 - ky*3;
            int iy = yy + ky - 1, ix = xx + kx - 1;
            va = ((unsigned)iy < 14u) && ((unsigned)ix < 14u);
            int iyc = va ? iy : 0, ixc = va ? ix : 0;
            sa = g_pool1 + (bb*196 + iyc*14 + ixc)*64;
        } else if constexpr (MODE == 2) {
            int kyx = it2 >> 1; int ky = kyx/3, kx = kyx - ky*3;
            sa = g_pool2 + (bb*36 + (yy+ky)*6 + (xx+kx))*128 + (it2&1)*64;
        } else {
            int kyx = it2 >> 1; int ky = kyx/3, kx = kyx - ky*3;
            sa = g_conv3 + (bb*16 + (yy+ky)*4 + (xx+kx))*128 + (it2&1)*64;
        }
        const bf16* sb = bptr + it2*64;
        sa += gb*8; sb += gb*8;
        #pragma unroll
        for (int g = 0; g < 4; g++) {
            cp16(aDst + so + g*16, sa + g*8, va);
            cp16(bDst + so + g*16, sb + g*8, true);
        }
    }
    asm volatile("cp.async.commit_group;\n");
}

template<int MODE>
__global__ void __launch_bounds__(256) gemm_kernel(
        const float* __restrict__ bias,
        const float* __restrict__ bias2,
        const int* __restrict__ ids,
        const int* __restrict__ oos,
        int K, int t, int nOff) {
    extern __shared__ __align__(16) char dsm[];
    uint32_t smBase = (uint32_t)__cvta_generic_to_shared(dsm);
    const int tid = threadIdx.x;
    const int m0 = blockIdx.x * 128;
    const int n0 = (blockIdx.y + nOff) * 128;

    const int rowS = tid >> 1;
    const int gb = (tid & 1) * 4;
    int bb = 0, yy = 0, xx = 0;
    {
        int m = m0 + rowS;
        if constexpr (MODE == 1) { bb = m/196; int p = m - bb*196; yy = p/14; xx = p - yy*14; }
        else if constexpr (MODE == 2) { bb = m >> 4; int p = m & 15; yy = p >> 2; xx = p & 3; }
        else if constexpr (MODE == 3) { bb = m >> 2; int p = m & 3;  yy = p >> 1; xx = p & 1; }
        else { bb = m; }
    }
    constexpr int LDK = (MODE == 0) ? 256 : (MODE == 4) ? 512 : (MODE == 1) ? 576 : 1152;
    const bf16* bptr = weightB<MODE>() + (size_t)(n0 + rowS) * LDK;
    const uint32_t aDst = smBase + rowS*144 + gb*16;
    const uint32_t bDst = smBase + 3*STG + rowS*144 + gb*16;

    const int nIter = K >> 6;

    const int lane = tid & 31, warp = tid >> 5;
    const int wm = (warp & 3)*32, wn = (warp >> 2)*64;
    const int r = lane >> 2, kc2 = (lane & 3)*2;
    const int lrow = (lane & 7) + ((lane >> 3) & 1)*8;
    const int lgA  = (lane >> 4) & 1;
    const uint32_t offA0 = (uint32_t)((wm + lrow)*144 + lgA*16);
    const uint32_t offA1 = offA0 + 16*144;
    const int q = lane >> 3;
    const int brow = (lane & 7) + (q >> 1)*8;
    const int bgl  = q & 1;
    uint32_t offB[4];
    #pragma unroll
    for (int jp = 0; jp < 4; jp++)
        offB[jp] = (uint32_t)((wn + jp*16 + brow)*144 + bgl*16);

    float4 acc[2][8];
    #pragma unroll
    for (int mi = 0; mi < 2; mi++)
        #pragma unroll
        for (int j = 0; j < 8; j++) acc[mi][j] = make_float4(0.f, 0.f, 0.f, 0.f);

    issue_stage<MODE>(0, nIter, bb, yy, xx, bptr, gb, aDst, bDst);
    issue_stage<MODE>(1, nIter, bb, yy, xx, bptr, gb, aDst, bDst);

    int st = 0;
    for (int it = 0; it < nIter; it++) {
        asm volatile("cp.async.wait_group 1;\n");
        __syncthreads();
        issue_stage<MODE>(it + 2, nIter, bb, yy, xx, bptr, gb, aDst, bDst);
        uint32_t sA = smBase + (uint32_t)st*STG;
        uint32_t sB = sA + 3*STG;
        #pragma unroll
        for (int s = 0; s < 4; s++) {
            uint32_t a00, a01, a02, a03, a10, a11, a12, a13;
            ldsm4(a00, a01, a02, a03, sA + offA0 + s*32);
            ldsm4(a10, a11, a12, a13, sA + offA1 + s*32);
            #pragma unroll
            for (int jp = 0; jp < 4; jp++) {
                uint32_t b0, b1, b2, b3;
                ldsm4(b0, b1, b2, b3, sB + offB[jp] + s*32);
                mma16(acc[0][2*jp  ], a00, a01, a02, a03, b0, b1);
                mma16(acc[0][2*jp+1], a00, a01, a02, a03, b2, b3);
                mma16(acc[1][2*jp  ], a10, a11, a12, a13, b0, b1);
                mma16(acc[1][2*jp+1], a10, a11, a12, a13, b2, b3);
            }
        }
        st = (st == 2) ? 0 : st + 1;
    }

    if constexpr (MODE == 4) {
        if (n0 < 2048) {
            #pragma unroll
            for (int mi = 0; mi < 2; mi++) {
                int row0 = m0 + wm + mi*16 + r, row1 = row0 + 8;
                int id0 = ids[row0*10 + t - 1], oo0 = oos[row0*10 + t - 1];
                int id1 = ids[row1*10 + t - 1], oo1 = oos[row1*10 + t - 1];
                #pragma unroll
                for (int j = 0; j < 8; j++) {
                    int col = n0 + wn + j*8 + kc2;
                    float4 d = acc[mi][j];
                    float2 e0 = *(const float2*)&g_embproj[row0*2048 + col];
                    float2 wa0 = *(const float2*)&g_wT[id0*2048 + col];
                    float2 wb0 = *(const float2*)&g_wT[(64 + oo0)*2048 + col];
                    *(float2*)&g_gates[row0*2048 + col] =
                        make_float2(d.x + e0.x + wa0.x + wb0.x, d.y + e0.y + wa0.y + wb0.y);
                    float2 e1 = *(const float2*)&g_embproj[row1*2048 + col];
                    float2 wa1 = *(const float2*)&g_wT[id1*2048 + col];
                    float2 wb1 = *(const float2*)&g_wT[(64 + oo1)*2048 + col];
                    *(float2*)&g_gates[row1*2048 + col] =
                        make_float2(d.z + e1.x + wa1.x + wb1.x, d.w + e1.y + wa1.y + wb1.y);
                }
            }
        } else {
            // logits tile: cols 2048..2175 -> g_logits[b*128 + cl], + lin_b (bias param)
            #pragma unroll
            for (int mi = 0; mi < 2; mi++) {
                int row0 = m0 + wm + mi*16 + r, row1 = row0 + 8;
                #pragma unroll
                for (int j = 0; j < 8; j++) {
                    int cl = wn + j*8 + kc2;   // 0..127
                    float b0 = (cl < 66) ? bias[cl] : 0.f;
                    float b1 = (cl + 1 < 66) ? bias[cl+1] : 0.f;
                    float4 d = acc[mi][j];
                    *(float2*)&g_logits[row0*128 + cl] = make_float2(d.x + b0, d.y + b1);
                    *(float2*)&g_logits[row1*128 + cl] = make_float2(d.z + b0, d.w + b1);
                }
            }
        }
    } else if constexpr (MODE == 0) {
        #pragma unroll
        for (int mi = 0; mi < 2; mi++) {
            int row0 = m0 + wm + mi*16 + r, row1 = row0 + 8;
            #pragma unroll
            for (int j = 0; j < 8; j++) {
                int col = n0 + wn + j*8 + kc2;
                float b0 = bias[col] + bias2[col], b1 = bias[col+1] + bias2[col+1];
                float4 d = acc[mi][j];
                *(float2*)&g_embproj[row0*2048 + col] = make_float2(d.x + b0, d.y + b1);
                *(float2*)&g_embproj[row1*2048 + col] = make_float2(d.z + b0, d.w + b1);
            }
        }
    } else {
        constexpr int LDO = (MODE == 3) ? 256 : 128;
        bf16* outp = (MODE == 1) ? g_conv2 : (MODE == 2) ? g_conv3 : g_conv4;
        #pragma unroll
        for (int mi = 0; mi < 2; mi++) {
            int row0 = m0 + wm + mi*16 + r, row1 = row0 + 8;
            #pragma unroll
            for (int j = 0; j < 8; j++) {
                int col = n0 + wn + j*8 + kc2;
                float b0 = bias[col], b1 = bias[col+1];
                float4 d = acc[mi][j];
                __nv_bfloat162 v0, v1;
                v0.x = __float2bfloat16_rn(fmaxf(d.x + b0, 0.f));
                v0.y = __float2bfloat16_rn(fmaxf(d.y + b1, 0.f));
                v1.x = __float2bfloat16_rn(fmaxf(d.z + b0, 0.f));
                v1.y = __float2bfloat16_rn(fmaxf(d.w + b1, 0.f));
                *(__nv_bfloat162*)&outp[row0*LDO + col] = v0;
                *(__nv_bfloat162*)&outp[row1*LDO + col] = v1;
            }
        }
    }
}

__global__ void pool2_kernel() {
    int idx = blockIdx.x*256 + threadIdx.x;
    if (idx >= B_*36*128) return;
    int c = idx & 127, rr = idx >> 7;
    int p = rr % 36, b = rr / 36;
    int py = p / 6, px = p % 6;
    float m = 0.f;
    #pragma unroll
    for (int dy = 0; dy < 3; dy++)
        #pragma unroll
        for (int dx = 0; dx < 3; dx++)
            m = fmaxf(m, __bfloat162float(g_conv2[(b*196 + (2*py+dy)*14 + 2*px+dx)*128 + c]));
    g_pool2[idx] = __float2bfloat16_rn(m);
}

__global__ void pool4_kernel() {
    int idx = blockIdx.x*256 + threadIdx.x;
    if (idx >= B_*256) return;
    int c = idx & 255, b = idx >> 8;
    const bf16* p = g_conv4 + b*1024 + c;
    float m = fmaxf(fmaxf(__bfloat162float(p[0]), __bfloat162float(p[256])),
                    fmaxf(__bfloat162float(p[512]), __bfloat162float(p[768])));
    g_emb[idx] = __float2bfloat16_rn(m);
}

// ---- warp softmax/gather over g_logits for step ts ----
__device__ __forceinline__ void softgather(int bw, int ts,
        const int* __restrict__ ids, const int* __restrict__ oos,
        float* __restrict__ out, float* lw, int lane) {
    float l0 = g_logits[bw*128 + lane];
    float l1 = g_logits[bw*128 + 32 + lane];
    float a2 = (lane < 2) ? g_logits[bw*128 + 64 + lane] : 0.f;
    float mx = fmaxf(l0, l1);
    #pragma unroll
    for (int o = 16; o > 0; o >>= 1) mx = fmaxf(mx, __shfl_xor_sync(0xffffffffu, mx, o));
    float s = expf(l0 - mx) + expf(l1 - mx);
    #pragma unroll
    for (int o = 16; o > 0; o >>= 1) s += __shfl_xor_sync(0xffffffffu, s, o);
    lw[lane] = l0; lw[lane+32] = l1;
    float a0 = __shfl_sync(0xffffffffu, a2, 0);
    float a1 = __shfl_sync(0xffffffffu, a2, 1);
    __syncwarp();
    if (lane == 0) {
        int idt = ids[bw*10 + ts], oot = oos[bw*10 + ts];
        float lp_id = lw[idt] - mx - logf(s);
        float mo = fmaxf(a0, a1);
        float ls = mo + logf(expf(a0 - mo) + expf(a1 - mo));
        float lp_oo = (oot ? a1 : a0) - ls;
        out[bw] += lp_id + (ts > 0 ? lp_oo : 0.f);
    }
}

// blocks 0..2047: cell for step t; blocks 2048..2175: softgather for step t-1
__global__ void __launch_bounds__(256) cellsoft_kernel(
        const int* __restrict__ ids, const int* __restrict__ oos,
        float* __restrict__ out, int t) {
    __shared__ float lw[8*64];
    const int blk = blockIdx.x, tid = threadIdx.x;
    if (blk < 2048) {
        int idx = blk*256 + tid;
        const float* gates = t ? g_gates : g_embproj;
        int b = idx >> 9, j = idx & 511;
        const float* g = gates + b*2048;
        float ig = g[j], fg = g[j+512], gg = g[j+1024], og = g[j+1536];
        float cp = g_c[idx];
        float si = 0.5f + 0.5f*tanha(0.5f*ig);
        float sf = 0.5f + 0.5f*tanha(0.5f*fg);
        float so = 0.5f + 0.5f*tanha(0.5f*og);
        float cc = sf*cp + si*tanha(gg);
        g_c[idx] = cc;
        g_h[idx] = __float2bfloat16_rn(so*tanha(cc));
    } else if (t >= 1) {
        int w = tid >> 5, lane = tid & 31;
        int bw = (blk - 2048)*8 + w;
        softgather(bw, t - 1, ids, oos, out, lw + w*64, lane);
    }
}

__global__ void __launch_bounds__(256) softfinal_kernel(
        const int* __restrict__ ids, const int* __restrict__ oos,
        float* __restrict__ out) {
    __shared__ float lw[8*64];
    int w = threadIdx.x >> 5, lane = threadIdx.x & 31;
    int bw = blockIdx.x*8 + w;
    softgather(bw, T_ - 1, ids, oos, out, lw + w*64, lane);
}

extern "C" void kernel_launch(void* const* d_in, const int* in_sizes, int n_in,
                              void* d_out, int out_size) {
    const float* obs  = (const float*)d_in[0];
    const int*   ids  = (const int*)  d_in[1];
    const int*   oos  = (const int*)  d_in[2];
    const float* cw1  = (const float*)d_in[3];
    const float* cb1  = (const float*)d_in[4];
    const float* cw2  = (const float*)d_in[5];
    const float* cb2  = (const float*)d_in[6];
    const float* cw3  = (const float*)d_in[7];
    const float* cb3  = (const float*)d_in[8];
    const float* cw4  = (const float*)d_in[9];
    const float* cb4  = (const float*)d_in[10];
    const float* w_ih = (const float*)d_in[11];
    const float* w_hh = (const float*)d_in[12];
    const float* b_ih = (const float*)d_in[13];
    const float* b_hh = (const float*)d_in[14];
    const float* lin_w= (const float*)d_in[15];
    const float* lin_b= (const float*)d_in[16];
    float* out = (float*)d_out;

    cudaFuncSetAttribute(gemm_kernel<0>, cudaFuncAttributeMaxDynamicSharedMemorySize, GEMM_SMEM);
    cudaFuncSetAttribute(gemm_kernel<1>, cudaFuncAttributeMaxDynamicSharedMemorySize, GEMM_SMEM);
    cudaFuncSetAttribute(gemm_kernel<2>, cudaFuncAttributeMaxDynamicSharedMemorySize, GEMM_SMEM);
    cudaFuncSetAttribute(gemm_kernel<3>, cudaFuncAttributeMaxDynamicSharedMemorySize, GEMM_SMEM);
    cudaFuncSetAttribute(gemm_kernel<4>, cudaFuncAttributeMaxDynamicSharedMemorySize, GEMM_SMEM);

    init_kernel<<<(B_*H_ + 255)/256, 256>>>(out);
    prep_kernel<<<(2257920 + 255)/256, 256>>>(cw2, cw3, cw4, w_ih, w_hh, lin_w);
    conv1_kernel<<<B_, 256>>>(obs, cw1, cb1);
    gemm_kernel<1><<<dim3(1568, 1), 256, GEMM_SMEM>>>(cb2, nullptr, nullptr, nullptr, 576, 0, 0);
    pool2_kernel<<<(B_*36*128 + 255)/256, 256>>>();
    gemm_kernel<2><<<dim3(128, 1), 256, GEMM_SMEM>>>(cb3, nullptr, nullptr, nullptr, 1152, 0, 0);
    gemm_kernel<3><<<dim3(32, 2), 256, GEMM_SMEM>>>(cb4, nullptr, nullptr, nullptr, 1152, 0, 0);
    pool4_kernel<<<(B_*256 + 255)/256, 256>>>();
    gemm_kernel<0><<<dim3(8, 16), 256, GEMM_SMEM>>>(b_ih, b_hh, nullptr, nullptr, 256, 0, 0);
    cellsoft_kernel<<<2176, 256>>>(ids, oos, out, 0);
    for (int t = 1; t < T_; t++) {
        // gates_t (tiles 0..15) + logits of h_{t-1} (tile 16)
        gemm_kernel<4><<<dim3(8, 17), 256, GEMM_SMEM>>>(lin_b, nullptr, ids, oos, 512, t, 0);
        cellsoft_kernel<<<2176, 256>>>(ids, oos, out, t);
    }
    // logits of h_9 only
    gemm_kernel<4><<<dim3(8, 1), 256, GEMM_SMEM>>>(lin_b, nullptr, ids, oos, 512, T_, 16);
    softfinal_kernel<<<128, 256>>>(ids, oos, out);
}